// round 5
// baseline (speedup 1.0000x reference)
#include <cuda_runtime.h>
#include <cuda_bf16.h>
#include <math.h>

// ---------------- problem constants ----------------
#define MAXN 50000
#define MAXE 800000
#define D12  256

// ---------------- scratch (device globals, compile-time symbol refs only) ---
__device__ float g_bufA[MAXN * D12];   // h (post-GEMM)
__device__ float g_bufB[MAXN * D12];   // aggregated output
__device__ float g_als[MAXN * 4];
__device__ float g_ald[MAXN * 4];
__device__ float g_prow[MAXN * 64];
__device__ float g_pcol[MAXN * 64];
__device__ int g_deg[MAXN];
__device__ int g_off[MAXN + 1];
__device__ int g_cur[MAXN];
__device__ int g_csr[MAXE];

// ---------------- CSR construction ----------------
__global__ void zero_deg_kernel(int n) {
    int i = blockIdx.x * blockDim.x + threadIdx.x;
    if (i < n) g_deg[i] = 0;
}

__global__ void hist_kernel(const int* ei, int E) {
    int i = blockIdx.x * blockDim.x + threadIdx.x;
    if (i < E) atomicAdd(&g_deg[ei[E + i]], 1);
}

__global__ void scan_kernel(int n) {
    __shared__ int sh[1024];
    __shared__ int s_carry;
    int tid = threadIdx.x;
    if (tid == 0) s_carry = 0;
    __syncthreads();
    for (int base = 0; base < n; base += 1024) {
        int v = (base + tid < n) ? g_deg[base + tid] : 0;
        sh[tid] = v;
        __syncthreads();
        for (int o = 1; o < 1024; o <<= 1) {
            int t2 = (tid >= o) ? sh[tid - o] : 0;
            __syncthreads();
            sh[tid] += t2;
            __syncthreads();
        }
        int incl = sh[tid];
        int c = s_carry;
        int total = sh[1023];
        if (base + tid < n) {
            int e = c + incl - v;
            g_off[base + tid] = e;
            g_cur[base + tid] = e;
        }
        __syncthreads();
        if (tid == 0) s_carry = c + total;
        __syncthreads();
    }
    if (tid == 0) g_off[n] = s_carry;
}

__global__ void scatter_kernel(const int* ei, int E) {
    int i = blockIdx.x * blockDim.x + threadIdx.x;
    if (i < E) {
        int d = ei[E + i];
        int s = ei[i];
        int p = atomicAdd(&g_cur[d], 1);
        g_csr[p] = s;
    }
}

// ---------------- 3xTF32 tensor-core GEMM ----------------
// C[M,Nc] = A[M,K] @ B[K,Nc], fp32-accurate via big/small tf32 split.
// Block tile 128(M) x 64(N), BK=16, 256 threads = 8 warps (4M x 2N),
// warp tile 32x32 = 2(m16) x 4(n8) mma tiles, mma.sync.m16n8k8.tf32.
// ASYM: false -> A = Aext; true -> A = g_bufB.
// CSEL: 0 -> g_bufA, 1 -> g_prow, 2 -> g_pcol.

__device__ __forceinline__ float tf32r(float x) {
    unsigned u;
    asm("cvt.rna.tf32.f32 %0, %1;" : "=r"(u) : "f"(x));
    return __uint_as_float(u);
}

__device__ __forceinline__ void mma_tf32(float& d0, float& d1, float& d2, float& d3,
                                         float a0, float a1, float a2, float a3,
                                         float b0, float b1) {
    asm volatile(
        "mma.sync.aligned.m16n8k8.row.col.f32.tf32.tf32.f32 "
        "{%0,%1,%2,%3}, {%4,%5,%6,%7}, {%8,%9}, {%0,%1,%2,%3};"
        : "+f"(d0), "+f"(d1), "+f"(d2), "+f"(d3)
        : "r"(__float_as_uint(a0)), "r"(__float_as_uint(a1)),
          "r"(__float_as_uint(a2)), "r"(__float_as_uint(a3)),
          "r"(__float_as_uint(b0)), "r"(__float_as_uint(b1)));
}

#define A_STRIDE 20   // conflict-free for quad fragment pattern
#define B_STRIDE 68

template <bool ASYM, int CSEL>
__global__ void gemm_tc_kernel(const float* Aext, const float* B, int M, int K, int Nc) {
    const float* A;
    if constexpr (ASYM) A = g_bufB; else A = Aext;
    float* C;
    if constexpr (CSEL == 0) C = g_bufA;
    else if constexpr (CSEL == 1) C = g_prow;
    else C = g_pcol;

    __shared__ float sAb[128 * A_STRIDE];
    __shared__ float sAs[128 * A_STRIDE];
    __shared__ float sBb[16 * B_STRIDE];
    __shared__ float sBs[16 * B_STRIDE];

    int tid = threadIdx.x;
    int bm = blockIdx.y * 128;
    int bn = blockIdx.x * 64;
    int warpId = tid >> 5;
    int lane = tid & 31;
    int g = lane >> 2;      // groupID
    int tg = lane & 3;      // thread in group
    int wRow = (warpId & 3) * 32;   // warp M offset within block
    int wCol = (warpId >> 2) * 32;  // warp N offset within block

    float d[2][4][4];
#pragma unroll
    for (int mi = 0; mi < 2; mi++)
#pragma unroll
        for (int ni = 0; ni < 4; ni++)
#pragma unroll
            for (int q = 0; q < 4; q++) d[mi][ni][q] = 0.f;

    // A tile load indices: 512 float4 / 256 threads = 2 each
    int aIdx0 = tid * 2;
    // B tile load: 256 float4 / 256 threads = 1 each
    int bIdx = tid;

    for (int k0 = 0; k0 < K; k0 += 16) {
        // load + split A tile [128][16]
#pragma unroll
        for (int i = 0; i < 2; i++) {
            int fl = aIdx0 + i;
            int r = fl >> 2;
            int c4 = (fl & 3) * 4;
            float4 v = make_float4(0.f, 0.f, 0.f, 0.f);
            if (bm + r < M) v = *(const float4*)(A + (size_t)(bm + r) * K + k0 + c4);
            float* pb = &sAb[r * A_STRIDE + c4];
            float* ps = &sAs[r * A_STRIDE + c4];
            float bx = tf32r(v.x); pb[0] = bx; ps[0] = tf32r(v.x - bx);
            float by = tf32r(v.y); pb[1] = by; ps[1] = tf32r(v.y - by);
            float bz = tf32r(v.z); pb[2] = bz; ps[2] = tf32r(v.z - bz);
            float bw = tf32r(v.w); pb[3] = bw; ps[3] = tf32r(v.w - bw);
        }
        // load + split B tile [16][64]
        {
            int r = bIdx >> 4;
            int c4 = (bIdx & 15) * 4;
            float4 v = *(const float4*)(B + (size_t)(k0 + r) * Nc + bn + c4);
            float* pb = &sBb[r * B_STRIDE + c4];
            float* ps = &sBs[r * B_STRIDE + c4];
            float bx = tf32r(v.x); pb[0] = bx; ps[0] = tf32r(v.x - bx);
            float by = tf32r(v.y); pb[1] = by; ps[1] = tf32r(v.y - by);
            float bz = tf32r(v.z); pb[2] = bz; ps[2] = tf32r(v.z - bz);
            float bw = tf32r(v.w); pb[3] = bw; ps[3] = tf32r(v.w - bw);
        }
        __syncthreads();

#pragma unroll
        for (int ks = 0; ks < 2; ks++) {
            int kc = ks * 8 + tg;
            // A fragments (big & small) for 2 m-tiles
            float ab[2][4], as_[2][4];
#pragma unroll
            for (int mi = 0; mi < 2; mi++) {
                int r = wRow + mi * 16 + g;
                ab[mi][0] = sAb[r * A_STRIDE + kc];
                ab[mi][1] = sAb[(r + 8) * A_STRIDE + kc];
                ab[mi][2] = sAb[r * A_STRIDE + kc + 4];
                ab[mi][3] = sAb[(r + 8) * A_STRIDE + kc + 4];
                as_[mi][0] = sAs[r * A_STRIDE + kc];
                as_[mi][1] = sAs[(r + 8) * A_STRIDE + kc];
                as_[mi][2] = sAs[r * A_STRIDE + kc + 4];
                as_[mi][3] = sAs[(r + 8) * A_STRIDE + kc + 4];
            }
#pragma unroll
            for (int ni = 0; ni < 4; ni++) {
                int ccol = wCol + ni * 8 + g;
                float bb0 = sBb[(ks * 8 + tg) * B_STRIDE + ccol];
                float bb1 = sBb[(ks * 8 + tg + 4) * B_STRIDE + ccol];
                float bs0 = sBs[(ks * 8 + tg) * B_STRIDE + ccol];
                float bs1 = sBs[(ks * 8 + tg + 4) * B_STRIDE + ccol];
#pragma unroll
                for (int mi = 0; mi < 2; mi++) {
                    float* dd = d[mi][ni];
                    mma_tf32(dd[0], dd[1], dd[2], dd[3],
                             ab[mi][0], ab[mi][1], ab[mi][2], ab[mi][3], bb0, bb1);
                    mma_tf32(dd[0], dd[1], dd[2], dd[3],
                             ab[mi][0], ab[mi][1], ab[mi][2], ab[mi][3], bs0, bs1);
                    mma_tf32(dd[0], dd[1], dd[2], dd[3],
                             as_[mi][0], as_[mi][1], as_[mi][2], as_[mi][3], bb0, bb1);
                }
            }
        }
        __syncthreads();
    }

    // epilogue
#pragma unroll
    for (int mi = 0; mi < 2; mi++) {
#pragma unroll
        for (int ni = 0; ni < 4; ni++) {
            int row0 = bm + wRow + mi * 16 + g;
            int col = bn + wCol + ni * 8 + tg * 2;
            if (row0 < M) {
                C[(size_t)row0 * Nc + col] = d[mi][ni][0];
                C[(size_t)row0 * Nc + col + 1] = d[mi][ni][1];
            }
            if (row0 + 8 < M) {
                C[(size_t)(row0 + 8) * Nc + col] = d[mi][ni][2];
                C[(size_t)(row0 + 8) * Nc + col + 1] = d[mi][ni][3];
            }
        }
    }
}

// ---------------- per-node attention coefficients ----------------
__global__ void al_kernel(const float* as, const float* ad, int N, int H, int C) {
    int gw = (blockIdx.x * blockDim.x + threadIdx.x) >> 5;
    int lane = threadIdx.x & 31;
    int n = gw / H;
    int hd = gw % H;
    if (n >= N) return;
    size_t base = (size_t)n * H * C + (size_t)hd * C;
    float s1 = 0.f, s2 = 0.f;
    for (int c = lane; c < C; c += 32) {
        float v = g_bufA[base + c];
        s1 = fmaf(v, as[hd * C + c], s1);
        s2 = fmaf(v, ad[hd * C + c], s2);
    }
#pragma unroll
    for (int o = 16; o; o >>= 1) {
        s1 += __shfl_down_sync(0xffffffffu, s1, o);
        s2 += __shfl_down_sync(0xffffffffu, s2, o);
    }
    if (lane == 0) {
        g_als[n * H + hd] = s1;
        g_ald[n * H + hd] = s2;
    }
}

// ---------------- GAT aggregation (block per dst node) ----------------
template <int H, int C>
__global__ void agg_kernel(const float* bias, int applyElu) {
    const int D = H * C;
    const int CHUNK = 64;
    int n = blockIdx.x;
    int t = threadIdx.x;
    __shared__ float sh_m[H];
    __shared__ float sh_iz[H];
    __shared__ float sh_alpha[CHUNK * H];
    __shared__ int sh_src[CHUNK];

    int o0 = g_off[n];
    int deg = g_off[n + 1] - o0;
    int wid = t >> 5, lane = t & 31;

    if (wid < H) {
        int hd = wid;
        float adn = g_ald[n * H + hd];
        float m = -1e30f, s = 0.f;
        for (int j = lane; j <= deg; j += 32) {
            int src = (j < deg) ? g_csr[o0 + j] : n;
            float att = g_als[src * H + hd] + adn;
            att = att > 0.f ? att : 0.2f * att;
            float mn = fmaxf(m, att);
            s = s * __expf(m - mn) + __expf(att - mn);
            m = mn;
        }
#pragma unroll
        for (int o = 16; o; o >>= 1) {
            float m2 = __shfl_down_sync(0xffffffffu, m, o);
            float s2 = __shfl_down_sync(0xffffffffu, s, o);
            float mn = fmaxf(m, m2);
            s = s * __expf(m - mn) + s2 * __expf(m2 - mn);
            m = mn;
        }
        if (lane == 0) {
            sh_m[hd] = m;
            sh_iz[hd] = 1.0f / s;
        }
    }
    __syncthreads();

    int head = t / C;
    float acc = 0.f;
    int total = deg + 1;
    for (int base = 0; base < total; base += CHUNK) {
        int cnt = min(CHUNK, total - base);
        if (t < CHUNK * H) {
            int j = t / H;
            int hd = t % H;
            if (j < cnt) {
                int src = (base + j < deg) ? g_csr[o0 + base + j] : n;
                if (hd == 0) sh_src[j] = src;
                float att = g_als[src * H + hd] + g_ald[n * H + hd];
                att = att > 0.f ? att : 0.2f * att;
                sh_alpha[j * H + hd] = __expf(att - sh_m[hd]) * sh_iz[hd];
            }
        }
        __syncthreads();
#pragma unroll 4
        for (int j = 0; j < cnt; j++) {
            acc = fmaf(g_bufA[(size_t)sh_src[j] * D + t], sh_alpha[j * H + head], acc);
        }
        __syncthreads();
    }
    float r = acc + bias[t];
    if (applyElu) r = r > 0.f ? r : expm1f(r);
    g_bufB[(size_t)n * D + t] = r;
}

// ---------------- edge MLP (warp per edge), factorized layer 1 ----------------
__global__ void edge_mlp_kernel(const int* ei, const float* ea,
                                const float* mw1, const float* mb1,
                                const float* mw2, const float* mb2,
                                const float* mw3, const float* mb3,
                                float* out, int E) {
    int warp = (int)((blockIdx.x * (size_t)blockDim.x + threadIdx.x) >> 5);
    int lane = threadIdx.x & 31;
    if (warp >= E) return;
    int row = ei[warp];
    int col = ei[E + warp];
    float ea0 = ea[warp * 2 + 0];
    float ea1 = ea[warp * 2 + 1];

    int j0 = lane, j1 = lane + 32;
    float o1a = g_prow[(size_t)row * 64 + j0] + g_pcol[(size_t)col * 64 + j0]
              + ea0 * mw1[256 * 64 + j0] + ea1 * mw1[257 * 64 + j0] + mb1[j0];
    float o1b = g_prow[(size_t)row * 64 + j1] + g_pcol[(size_t)col * 64 + j1]
              + ea0 * mw1[256 * 64 + j1] + ea1 * mw1[257 * 64 + j1] + mb1[j1];
    o1a = fmaxf(o1a, 0.f);
    o1b = fmaxf(o1b, 0.f);

    float acc = mb2[lane];
#pragma unroll
    for (int j = 0; j < 32; j++) {
        float va = __shfl_sync(0xffffffffu, o1a, j);
        float vb = __shfl_sync(0xffffffffu, o1b, j);
        acc = fmaf(va, mw2[j * 32 + lane], acc);
        acc = fmaf(vb, mw2[(j + 32) * 32 + lane], acc);
    }
    acc = fmaxf(acc, 0.f);

    float v = acc * mw3[lane];
#pragma unroll
    for (int o = 16; o; o >>= 1) v += __shfl_down_sync(0xffffffffu, v, o);
    if (lane == 0) out[warp] = v + mb3[0];
}

// ---------------- launch ----------------
extern "C" void kernel_launch(void* const* d_in, const int* in_sizes, int n_in,
                              void* d_out, int out_size) {
    const float* x = (const float*)d_in[0];
    const int* ei = (const int*)d_in[1];       // int32 (JAX demotes int64)
    const float* ea = (const float*)d_in[2];
    const float* W1 = (const float*)d_in[3];
    const float* a1s = (const float*)d_in[4];
    const float* a1d = (const float*)d_in[5];
    const float* b1 = (const float*)d_in[6];
    const float* W2 = (const float*)d_in[7];
    const float* a2s = (const float*)d_in[8];
    const float* a2d = (const float*)d_in[9];
    const float* b2 = (const float*)d_in[10];
    const float* W3 = (const float*)d_in[11];
    const float* a3s = (const float*)d_in[12];
    const float* a3d = (const float*)d_in[13];
    const float* b3 = (const float*)d_in[14];
    const float* mw1 = (const float*)d_in[15];
    const float* mb1 = (const float*)d_in[16];
    const float* mw2 = (const float*)d_in[17];
    const float* mb2 = (const float*)d_in[18];
    const float* mw3 = (const float*)d_in[19];
    const float* mb3 = (const float*)d_in[20];
    float* out = (float*)d_out;

    int N = in_sizes[0] / 32;
    int E = in_sizes[1] / 2;

    // ---- CSR build (by dst) ----
    zero_deg_kernel<<<(N + 255) / 256, 256>>>(N);
    hist_kernel<<<(E + 255) / 256, 256>>>(ei, E);
    scan_kernel<<<1, 1024>>>(N);
    scatter_kernel<<<(E + 255) / 256, 256>>>(ei, E);

    int mBlocks = (N + 127) / 128;
    dim3 g256(256 / 64, mBlocks);
    dim3 g128(128 / 64, mBlocks);
    dim3 g64(64 / 64, mBlocks);

    int alBlocks4 = ((N * 4) * 32 + 255) / 256;
    int alBlocks1 = ((N * 1) * 32 + 255) / 256;

    // ---- layer 1 ----
    gemm_tc_kernel<false, 0><<<g256, 256>>>(x, W1, N, 32, 256);   // x -> g_bufA
    al_kernel<<<alBlocks4, 256>>>(a1s, a1d, N, 4, 64);
    agg_kernel<4, 64><<<N, 256>>>(b1, 1);                          // -> g_bufB

    // ---- layer 2 ----
    gemm_tc_kernel<true, 0><<<g256, 256>>>(x, W2, N, 256, 256);
    al_kernel<<<alBlocks4, 256>>>(a2s, a2d, N, 4, 64);
    agg_kernel<4, 64><<<N, 256>>>(b2, 1);

    // ---- layer 3 (1 head, 128 ch, no ELU) ----
    gemm_tc_kernel<true, 0><<<g128, 256>>>(x, W3, N, 256, 128);
    al_kernel<<<alBlocks1, 256>>>(a3s, a3d, N, 1, 128);
    agg_kernel<1, 128><<<N, 128>>>(b3, 0);

    // ---- edge MLP precompute ----
    gemm_tc_kernel<true, 1><<<g64, 256>>>(x, mw1, N, 128, 64);
    gemm_tc_kernel<true, 2><<<g64, 256>>>(x, mw1 + 128 * 64, N, 128, 64);

    // ---- edge MLP ----
    int warpsPerBlock = 8;
    int blocks = (E + warpsPerBlock - 1) / warpsPerBlock;
    edge_mlp_kernel<<<blocks, warpsPerBlock * 32>>>(ei, ea, mw1, mb1, mw2,
                                                    mb2, mw3, mb3, out, E);
}